// round 1
// baseline (speedup 1.0000x reference)
#include <cuda_runtime.h>
#include <math.h>
#include <stdint.h>

// Problem constants
#define BB   128
#define DD   256
#define SS   512
#define KK   50
#define HH   256
#define NROW 65536           // B*S
#define OUT_PRED   0         // 256 floats
#define OUT_ZERO   256
#define OUT_CSIM   257
#define OUT_CFAR   258
#define OUT_TPNN   259       // 3,276,800 floats
#define OUT_AE     3277059

// -------- scratch (static device memory; no allocations allowed) --------
__device__ float g_tvn[DD * KK];                 // normalized topic vectors [d][k]
__device__ float g_rnorm[NROW];                  // 1/max(||x_row||,1e-12)
__device__ float g_tpnT[(size_t)KK * NROW];      // topic_prob_n transposed [k][row]
__device__ float g_rec1o[(size_t)NROW * HH];     // relu(nn @ rec1)  (64 MB)
__device__ float g_predpart[512 * 256];          // per (row-tile, d) column sums
__device__ float g_aepart[1024];                 // per-CTA ae partials (kernelB grid)
__device__ float g_topsum[KK];                   // per-concept top-32 sums

// ======================= prep: tv_n + concept_far =======================
__global__ void prep_kernel(const float* __restrict__ tv, float* __restrict__ out) {
    __shared__ float cinv[64];
    __shared__ float sd[DD];
    int t = threadIdx.x;                 // 256 threads
    if (t < KK) {
        float s = 0.f;
        for (int d = 0; d < DD; d++) { float v = tv[d * KK + t]; s += v * v; }
        cinv[t] = 1.0f / fmaxf(sqrtf(s), 1e-12f);
    }
    __syncthreads();
    {   // thread t == d
        float sum = 0.f;
        for (int k = 0; k < KK; k++) {
            float v = tv[t * KK + k] * cinv[k];
            g_tvn[t * KK + k] = v;
            sum += v;
        }
        sd[t] = sum;
    }
    __syncthreads();
    if (t == 0) {
        float g = 0.f;
        for (int d = 0; d < DD; d++) g += sd[d] * sd[d];   // sum of Gram matrix
        out[OUT_CFAR] = (g - (float)KK) / (float)(KK * KK);
        out[OUT_ZERO] = 0.0f;
    }
}

// =================== kernelA: topic path + rec1 =========================
// grid: 512 CTAs (b 0..127, s-tile 0..3), 512 threads, 128 rows per CTA
#define XS_F  (256 * 128)
#define TVS_F (256 * 52)
#define TPS_F (128 * 52)
#define SMEM_A_BYTES ((XS_F + TVS_F + TPS_F + 128 + 512) * 4)

__global__ void __launch_bounds__(512) kernelA(const float* __restrict__ fin,
                                               const float* __restrict__ rec1,
                                               float* __restrict__ out) {
    extern __shared__ float sm[];
    float* xs  = sm;                   // [256 d][128 j]
    float* tvs = xs + XS_F;            // [256 d][52 k] (later rec1 [50][256])
    float* tps = tvs + TVS_F;          // [128 j][52 k]
    float* rn  = tps + TPS_F;          // [128]  (rnorm, later 1/(sum+eps))
    float* ps  = rn + 128;             // [128][4]

    int t = threadIdx.x;
    int cid = blockIdx.x;
    int b = cid >> 2, st = cid & 3;
    int s0 = st * 128;
    int row0 = b * SS + s0;
    const float* fb = fin + (size_t)b * DD * SS + s0;

    // load x tile (coalesced over s)
    #pragma unroll 4
    for (int it = 0; it < 64; it++) {
        int idx = t + 512 * it;
        int d = idx >> 7, j = idx & 127;
        xs[d * 128 + j] = fb[(size_t)d * SS + j];
    }
    // load tv_n padded to 52 cols
    for (int idx = t; idx < TVS_F; idx += 512) {
        int d = idx / 52, k = idx - d * 52;
        tvs[idx] = (k < KK) ? g_tvn[d * KK + k] : 0.0f;
    }
    __syncthreads();

    // row norms: 4 threads per row
    {
        int j = t >> 2, q = t & 3;
        const float* xp = xs + (q * 64) * 128 + j;
        float s = 0.f;
        #pragma unroll 8
        for (int d = 0; d < 64; d++) { float v = xp[d * 128]; s += v * v; }
        ps[j * 4 + q] = s;
    }
    __syncthreads();
    if (t < 128) {
        float s = ps[t * 4] + ps[t * 4 + 1] + ps[t * 4 + 2] + ps[t * 4 + 3];
        float r = 1.0f / fmaxf(sqrtf(s), 1e-12f);
        rn[t] = r;
        g_rnorm[row0 + t] = r;
    }
    __syncthreads();

    // topic dots: 32 j-tiles x 13 k-tiles, 4x4 register tiles
    if (t < 416) {
        int jt = t / 13, kt = t - jt * 13;
        const float* xb = xs + jt * 4;
        const float* tb = tvs + kt * 4;
        float acc[4][4] = {};
        #pragma unroll 4
        for (int d = 0; d < DD; d++) {
            float4 xv = *(const float4*)(xb + d * 128);
            float4 tw = *(const float4*)(tb + d * 52);
            float xr[4] = {xv.x, xv.y, xv.z, xv.w};
            float tr[4] = {tw.x, tw.y, tw.z, tw.w};
            #pragma unroll
            for (int r = 0; r < 4; r++)
                #pragma unroll
                for (int c = 0; c < 4; c++)
                    acc[r][c] += xr[r] * tr[c];
        }
        #pragma unroll
        for (int r = 0; r < 4; r++)
            #pragma unroll
            for (int c = 0; c < 4; c++)
                tps[(jt * 4 + r) * 52 + kt * 4 + c] = acc[r][c];
    }
    __syncthreads();

    // mask / sum : 4 threads per row
    int j = t >> 2, q = t & 3;
    int gRow = row0 + j;
    {
        float partial = 0.f;
        float rj = rn[j];
        #pragma unroll
        for (int i = 0; i < 13; i++) {
            int k = q + 4 * i;
            if (k < KK) {
                float tp = tps[j * 52 + k];
                float tpn = tp * rj;
                g_tpnT[(size_t)k * NROW + gRow] = tpn;
                float m = (tpn > 0.3f) ? tp : 0.0f;
                tps[j * 52 + k] = m;
                partial += m;
            }
        }
        ps[j * 4 + q] = partial;
    }
    __syncthreads();
    if (t < 128) {
        float s = ps[t * 4] + ps[t * 4 + 1] + ps[t * 4 + 2] + ps[t * 4 + 3];
        rn[t] = 1.0f / (s + 0.001f + 1e-8f);    // reuse rn as inv-denominator
    }
    __syncthreads();
    {
        float inv = rn[j];
        float* tpnn = out + OUT_TPNN;
        #pragma unroll
        for (int i = 0; i < 13; i++) {
            int k = q + 4 * i;
            if (k < KK) {
                float nv = tps[j * 52 + k] * inv;
                tps[j * 52 + k] = nv;
                tpnn[(size_t)gRow * KK + k] = nv;
            }
        }
    }
    __syncthreads();

    // load rec1 [50][256] into tvs region (12800 <= 13312)
    for (int idx = t; idx < KK * HH; idx += 512) tvs[idx] = rec1[idx];
    __syncthreads();

    // rec1out = relu(nn @ rec1): 32 j-tiles x 64 h-tiles, 4 tiles per thread
    #pragma unroll
    for (int it = 0; it < 4; it++) {
        int idx = t + 512 * it;
        int jt = idx >> 6, ht = idx & 63;
        int j0 = jt * 4, h0 = ht * 4;
        float acc[4][4] = {};
        #pragma unroll 2
        for (int k = 0; k < KK; k++) {
            float nv[4];
            #pragma unroll
            for (int r = 0; r < 4; r++) nv[r] = tps[(j0 + r) * 52 + k];
            float4 rv = *(const float4*)(tvs + k * HH + h0);
            float rr[4] = {rv.x, rv.y, rv.z, rv.w};
            #pragma unroll
            for (int r = 0; r < 4; r++)
                #pragma unroll
                for (int c = 0; c < 4; c++)
                    acc[r][c] += nv[r] * rr[c];
        }
        #pragma unroll
        for (int r = 0; r < 4; r++) {
            float4 o;
            o.x = fmaxf(acc[r][0], 0.f); o.y = fmaxf(acc[r][1], 0.f);
            o.z = fmaxf(acc[r][2], 0.f); o.w = fmaxf(acc[r][3], 0.f);
            *(float4*)(g_rec1o + (size_t)(row0 + j0 + r) * HH + h0) = o;
        }
    }
}

// =================== kernelB: rec2 GEMM + fused ae/pred ==================
// grid (nt=2, mt=512), 256 threads, 128x128 tile, thread 8x8
__global__ void __launch_bounds__(256, 2) kernelB(const float* __restrict__ fin,
                                                  const float* __restrict__ rec2) {
    __shared__ float As[16 * 132];
    __shared__ float Bs[16 * 132];
    __shared__ float rns[128];

    int t = threadIdx.x;
    int tx = t & 15, ty = t >> 4;
    int mt = blockIdx.y, nt = blockIdx.x;
    int row0 = mt * 128;
    int n0 = nt * 128;
    int b = row0 >> 9;
    int sbase = row0 & 511;

    if (t < 128) rns[t] = g_rnorm[row0 + t];

    int rA0 = t >> 2, kkoA = t & 3;           // A-load ids (and rA0+64)
    int kkB0 = t >> 5, c4B = t & 31;          // B-load ids (and kkB0+8)

    float acc[8][8] = {};

    // prologue
    float4 a0 = *(const float4*)&g_rec1o[(size_t)(row0 + rA0) * HH + kkoA * 4];
    float4 a1 = *(const float4*)&g_rec1o[(size_t)(row0 + rA0 + 64) * HH + kkoA * 4];
    float4 b0 = *(const float4*)&rec2[(size_t)kkB0 * DD + n0 + c4B * 4];
    float4 b1 = *(const float4*)&rec2[(size_t)(kkB0 + 8) * DD + n0 + c4B * 4];
    {
        As[(kkoA * 4 + 0) * 132 + rA0] = a0.x; As[(kkoA * 4 + 1) * 132 + rA0] = a0.y;
        As[(kkoA * 4 + 2) * 132 + rA0] = a0.z; As[(kkoA * 4 + 3) * 132 + rA0] = a0.w;
        As[(kkoA * 4 + 0) * 132 + rA0 + 64] = a1.x; As[(kkoA * 4 + 1) * 132 + rA0 + 64] = a1.y;
        As[(kkoA * 4 + 2) * 132 + rA0 + 64] = a1.z; As[(kkoA * 4 + 3) * 132 + rA0 + 64] = a1.w;
        *(float4*)&Bs[kkB0 * 132 + c4B * 4] = b0;
        *(float4*)&Bs[(kkB0 + 8) * 132 + c4B * 4] = b1;
    }
    __syncthreads();

    for (int kt = 0; kt < 16; kt++) {
        if (kt < 15) {
            int k0 = (kt + 1) * 16;
            a0 = *(const float4*)&g_rec1o[(size_t)(row0 + rA0) * HH + k0 + kkoA * 4];
            a1 = *(const float4*)&g_rec1o[(size_t)(row0 + rA0 + 64) * HH + k0 + kkoA * 4];
            b0 = *(const float4*)&rec2[(size_t)(k0 + kkB0) * DD + n0 + c4B * 4];
            b1 = *(const float4*)&rec2[(size_t)(k0 + kkB0 + 8) * DD + n0 + c4B * 4];
        }
        #pragma unroll
        for (int kk = 0; kk < 16; kk++) {
            float ar[8], br[8];
            #pragma unroll
            for (int i = 0; i < 8; i++) ar[i] = As[kk * 132 + tx + 16 * i];
            float4 bv0 = *(const float4*)&Bs[kk * 132 + ty * 8];
            float4 bv1 = *(const float4*)&Bs[kk * 132 + ty * 8 + 4];
            br[0] = bv0.x; br[1] = bv0.y; br[2] = bv0.z; br[3] = bv0.w;
            br[4] = bv1.x; br[5] = bv1.y; br[6] = bv1.z; br[7] = bv1.w;
            #pragma unroll
            for (int i = 0; i < 8; i++)
                #pragma unroll
                for (int c = 0; c < 8; c++)
                    acc[i][c] += ar[i] * br[c];
        }
        __syncthreads();
        if (kt < 15) {
            As[(kkoA * 4 + 0) * 132 + rA0] = a0.x; As[(kkoA * 4 + 1) * 132 + rA0] = a0.y;
            As[(kkoA * 4 + 2) * 132 + rA0] = a0.z; As[(kkoA * 4 + 3) * 132 + rA0] = a0.w;
            As[(kkoA * 4 + 0) * 132 + rA0 + 64] = a1.x; As[(kkoA * 4 + 1) * 132 + rA0 + 64] = a1.y;
            As[(kkoA * 4 + 2) * 132 + rA0 + 64] = a1.z; As[(kkoA * 4 + 3) * 132 + rA0 + 64] = a1.w;
            *(float4*)&Bs[kkB0 * 132 + c4B * 4] = b0;
            *(float4*)&Bs[(kkB0 + 8) * 132 + c4B * 4] = b1;
            __syncthreads();
        }
    }

    // epilogue: ae partial + column sums (rec2out never stored)
    float aeacc = 0.f;
    float colsum[8] = {};
    const float* fbase = fin + (size_t)b * DD * SS;
    #pragma unroll
    for (int i = 0; i < 8; i++) {
        int r = tx + 16 * i;
        float rnv = rns[r];
        int s = sbase + r;
        #pragma unroll
        for (int c = 0; c < 8; c++) {
            int d = n0 + ty * 8 + c;
            float o = acc[i][c];
            float xn = fbase[(size_t)d * SS + s] * rnv;
            float df = xn - o;
            aeacc += df * df;
            colsum[c] += o;
        }
    }
    __syncthreads();
    // pred column-sum reduce (reuse As as [16 tx][128 d])
    #pragma unroll
    for (int c = 0; c < 8; c++) As[tx * 128 + ty * 8 + c] = colsum[c];
    Bs[t] = aeacc;
    __syncthreads();
    if (t < 128) {
        float s = 0.f;
        #pragma unroll
        for (int x = 0; x < 16; x++) s += As[x * 128 + t];
        g_predpart[mt * 256 + n0 + t] = s;
    }
    for (int off = 128; off > 0; off >>= 1) {
        if (t < off) Bs[t] += Bs[t + off];
        __syncthreads();
    }
    if (t == 0) g_aepart[mt * 2 + nt] = Bs[0];
}

// =================== kernelC: per-concept top-32 sum =====================
__global__ void __launch_bounds__(256) kernelC() {
    int k = blockIdx.x, t = threadIdx.x;
    const float* col = g_tpnT + (size_t)k * NROW;
    float top[32];
    #pragma unroll
    for (int i = 0; i < 32; i++) top[i] = -1e30f;
    for (int i = 0; i < 256; i++) {
        float v = col[t + 256 * i];
        if (v > top[31]) {
            #pragma unroll
            for (int a = 0; a < 32; a++) {
                if (v > top[a]) { float tmp = top[a]; top[a] = v; v = tmp; }
            }
        }
    }
    __shared__ float cand[256 * 32];
    __shared__ float rmax[256];
    __shared__ int   rarg[256];
    #pragma unroll
    for (int i = 0; i < 32; i++) cand[t * 32 + i] = top[i];
    __syncthreads();

    int ptr = 0;
    float sum0 = 0.f;
    for (int round = 0; round < 32; round++) {
        rmax[t] = cand[t * 32 + ptr];
        rarg[t] = t;
        __syncthreads();
        for (int off = 128; off > 0; off >>= 1) {
            if (t < off) {
                if (rmax[t + off] > rmax[t]) { rmax[t] = rmax[t + off]; rarg[t] = rarg[t + off]; }
            }
            __syncthreads();
        }
        if (t == 0) sum0 += rmax[0];
        int w = rarg[0];
        __syncthreads();
        if (t == w) ptr++;
    }
    if (t == 0) g_topsum[k] = sum0;
}

// =================== final: reductions + pred head =======================
__global__ void __launch_bounds__(256) finalK(const float* __restrict__ Wc,
                                              const float* __restrict__ bc,
                                              float* __restrict__ out) {
    __shared__ float red[256];
    int t = threadIdx.x;
    float s = 0.f;
    for (int i = t; i < 1024; i += 256) s += g_aepart[i];
    red[t] = s;
    __syncthreads();
    for (int off = 128; off > 0; off >>= 1) {
        if (t < off) red[t] += red[t + off];
        __syncthreads();
    }
    if (t == 0) {
        out[OUT_AE] = red[0] / 16777216.0f;
        float cs = 0.f;
        for (int k = 0; k < KK; k++) cs += g_topsum[k];
        out[OUT_CSIM] = -cs / 1600.0f;
    }
    // pred: thread = b*2 + cls
    {
        int bi = t >> 1, c = t & 1;
        float acc = 0.f;
        for (int d = 0; d < DD; d++) {
            float rs = g_predpart[(bi * 4 + 0) * 256 + d]
                     + g_predpart[(bi * 4 + 1) * 256 + d]
                     + g_predpart[(bi * 4 + 2) * 256 + d]
                     + g_predpart[(bi * 4 + 3) * 256 + d];
            acc += rs * Wc[d * 2 + c];
        }
        out[bi * 2 + c] = acc * (1.0f / 512.0f) + bc[c];
    }
}

// ============================ launcher ===================================
extern "C" void kernel_launch(void* const* d_in, const int* in_sizes, int n_in,
                              void* d_out, int out_size) {
    const float* f_input      = (const float*)d_in[0];
    // d_in[1] targets: unused by the reference outputs
    const float* topic_vector = (const float*)d_in[2];
    const float* rec1         = (const float*)d_in[3];
    const float* rec2         = (const float*)d_in[4];
    const float* Wc           = (const float*)d_in[5];
    const float* bc           = (const float*)d_in[6];
    float* out = (float*)d_out;

    cudaFuncSetAttribute(kernelA, cudaFuncAttributeMaxDynamicSharedMemorySize, SMEM_A_BYTES);

    prep_kernel<<<1, 256>>>(topic_vector, out);
    kernelA<<<512, 512, SMEM_A_BYTES>>>(f_input, rec1, out);
    kernelB<<<dim3(2, 512), 256>>>(f_input, rec2);
    kernelC<<<KK, 256>>>();
    finalK<<<1, 256>>>(Wc, bc, out);
}

// round 2
// speedup vs baseline: 1.2291x; 1.2291x over previous
#include <cuda_runtime.h>
#include <math.h>
#include <stdint.h>

// Problem constants
#define BB   128
#define DD   256
#define SS   512
#define KK   50
#define HH   256
#define NROW 65536           // B*S
#define OUT_PRED   0         // 256 floats
#define OUT_ZERO   256
#define OUT_CSIM   257
#define OUT_CFAR   258
#define OUT_TPNN   259       // 3,276,800 floats
#define OUT_AE     3277059

// -------- scratch (static device memory; no allocations allowed) --------
__device__ float g_tvn[DD * KK];                 // normalized topic vectors [d][k]
__device__ float g_rnorm[NROW];                  // 1/max(||x_row||,1e-12)
__device__ float g_tpnT[(size_t)KK * NROW];      // topic_prob_n transposed [k][row]
__device__ float g_rec1o[(size_t)NROW * HH];     // relu(nn @ rec1)  (64 MB)
__device__ float g_predpart[512 * 256];          // per (row-tile, d) column sums
__device__ float g_aepart[1024];                 // per-CTA ae partials (kernelB grid)
__device__ float g_topsum[KK];                   // per-concept top-32 sums
// top-k selection scratch
__device__ int   g_hist[KK * 128];               // per-concept value histogram
__device__ int   g_bstar[KK];                    // selected threshold bin
__device__ int   g_candcnt[KK];                  // candidate counts
__device__ float g_cand[(size_t)KK * NROW];      // candidate values (worst case)

// ======================= prep: tv_n + concept_far + zero scratch ========
__global__ void prep_kernel(const float* __restrict__ tv, float* __restrict__ out) {
    __shared__ float cinv[64];
    __shared__ float sd[DD];
    int t = threadIdx.x;                 // 256 threads
    // zero top-k scratch (must be per-launch for determinism)
    for (int i = t; i < KK * 128; i += 256) g_hist[i] = 0;
    if (t < KK) g_candcnt[t] = 0;
    if (t < KK) {
        float s = 0.f;
        for (int d = 0; d < DD; d++) { float v = tv[d * KK + t]; s += v * v; }
        cinv[t] = 1.0f / fmaxf(sqrtf(s), 1e-12f);
    }
    __syncthreads();
    {   // thread t == d
        float sum = 0.f;
        for (int k = 0; k < KK; k++) {
            float v = tv[t * KK + k] * cinv[k];
            g_tvn[t * KK + k] = v;
            sum += v;
        }
        sd[t] = sum;
    }
    __syncthreads();
    if (t == 0) {
        float g = 0.f;
        for (int d = 0; d < DD; d++) g += sd[d] * sd[d];   // sum of Gram matrix
        out[OUT_CFAR] = (g - (float)KK) / (float)(KK * KK);
        out[OUT_ZERO] = 0.0f;
    }
}

// =================== kernelA: topic path + rec1 =========================
// grid: 512 CTAs (b 0..127, s-tile 0..3), 512 threads, 128 rows per CTA
#define XS_F  (256 * 128)
#define TVS_F (256 * 52)
#define TPS_F (128 * 52)
#define SMEM_A_BYTES ((XS_F + TVS_F + TPS_F + 128 + 512) * 4)

__global__ void __launch_bounds__(512) kernelA(const float* __restrict__ fin,
                                               const float* __restrict__ rec1,
                                               float* __restrict__ out) {
    extern __shared__ float sm[];
    float* xs  = sm;                   // [256 d][128 j]
    float* tvs = xs + XS_F;            // [256 d][52 k] (later rec1 [50][256])
    float* tps = tvs + TVS_F;          // [128 j][52 k]
    float* rn  = tps + TPS_F;          // [128]  (rnorm, later 1/(sum+eps))
    float* ps  = rn + 128;             // [128][4]

    int t = threadIdx.x;
    int cid = blockIdx.x;
    int b = cid >> 2, st = cid & 3;
    int s0 = st * 128;
    int row0 = b * SS + s0;
    const float* fb = fin + (size_t)b * DD * SS + s0;

    // load x tile (coalesced over s)
    #pragma unroll 4
    for (int it = 0; it < 64; it++) {
        int idx = t + 512 * it;
        int d = idx >> 7, j = idx & 127;
        xs[d * 128 + j] = fb[(size_t)d * SS + j];
    }
    // load tv_n padded to 52 cols
    for (int idx = t; idx < TVS_F; idx += 512) {
        int d = idx / 52, k = idx - d * 52;
        tvs[idx] = (k < KK) ? g_tvn[d * KK + k] : 0.0f;
    }
    __syncthreads();

    // row norms: 4 threads per row
    {
        int j = t >> 2, q = t & 3;
        const float* xp = xs + (q * 64) * 128 + j;
        float s = 0.f;
        #pragma unroll 8
        for (int d = 0; d < 64; d++) { float v = xp[d * 128]; s += v * v; }
        ps[j * 4 + q] = s;
    }
    __syncthreads();
    if (t < 128) {
        float s = ps[t * 4] + ps[t * 4 + 1] + ps[t * 4 + 2] + ps[t * 4 + 3];
        float r = 1.0f / fmaxf(sqrtf(s), 1e-12f);
        rn[t] = r;
        g_rnorm[row0 + t] = r;
    }
    __syncthreads();

    // topic dots: 32 j-tiles x 13 k-tiles, 4x4 register tiles
    if (t < 416) {
        int jt = t / 13, kt = t - jt * 13;
        const float* xb = xs + jt * 4;
        const float* tb = tvs + kt * 4;
        float acc[4][4] = {};
        #pragma unroll 4
        for (int d = 0; d < DD; d++) {
            float4 xv = *(const float4*)(xb + d * 128);
            float4 tw = *(const float4*)(tb + d * 52);
            float xr[4] = {xv.x, xv.y, xv.z, xv.w};
            float tr[4] = {tw.x, tw.y, tw.z, tw.w};
            #pragma unroll
            for (int r = 0; r < 4; r++)
                #pragma unroll
                for (int c = 0; c < 4; c++)
                    acc[r][c] += xr[r] * tr[c];
        }
        #pragma unroll
        for (int r = 0; r < 4; r++)
            #pragma unroll
            for (int c = 0; c < 4; c++)
                tps[(jt * 4 + r) * 52 + kt * 4 + c] = acc[r][c];
    }
    __syncthreads();

    // mask / sum : 4 threads per row
    int j = t >> 2, q = t & 3;
    int gRow = row0 + j;
    {
        float partial = 0.f;
        float rj = rn[j];
        #pragma unroll
        for (int i = 0; i < 13; i++) {
            int k = q + 4 * i;
            if (k < KK) {
                float tp = tps[j * 52 + k];
                float tpn = tp * rj;
                g_tpnT[(size_t)k * NROW + gRow] = tpn;
                float m = (tpn > 0.3f) ? tp : 0.0f;
                tps[j * 52 + k] = m;
                partial += m;
            }
        }
        ps[j * 4 + q] = partial;
    }
    __syncthreads();
    if (t < 128) {
        float s = ps[t * 4] + ps[t * 4 + 1] + ps[t * 4 + 2] + ps[t * 4 + 3];
        rn[t] = 1.0f / (s + 0.001f + 1e-8f);    // reuse rn as inv-denominator
    }
    __syncthreads();
    {
        float inv = rn[j];
        float* tpnn = out + OUT_TPNN;
        #pragma unroll
        for (int i = 0; i < 13; i++) {
            int k = q + 4 * i;
            if (k < KK) {
                float nv = tps[j * 52 + k] * inv;
                tps[j * 52 + k] = nv;
                tpnn[(size_t)gRow * KK + k] = nv;
            }
        }
    }
    __syncthreads();

    // load rec1 [50][256] into tvs region (12800 <= 13312)
    for (int idx = t; idx < KK * HH; idx += 512) tvs[idx] = rec1[idx];
    __syncthreads();

    // rec1out = relu(nn @ rec1): 32 j-tiles x 64 h-tiles, 4 tiles per thread
    #pragma unroll
    for (int it = 0; it < 4; it++) {
        int idx = t + 512 * it;
        int jt = idx >> 6, ht = idx & 63;
        int j0 = jt * 4, h0 = ht * 4;
        float acc[4][4] = {};
        #pragma unroll 2
        for (int k = 0; k < KK; k++) {
            float nv[4];
            #pragma unroll
            for (int r = 0; r < 4; r++) nv[r] = tps[(j0 + r) * 52 + k];
            float4 rv = *(const float4*)(tvs + k * HH + h0);
            float rr[4] = {rv.x, rv.y, rv.z, rv.w};
            #pragma unroll
            for (int r = 0; r < 4; r++)
                #pragma unroll
                for (int c = 0; c < 4; c++)
                    acc[r][c] += nv[r] * rr[c];
        }
        #pragma unroll
        for (int r = 0; r < 4; r++) {
            float4 o;
            o.x = fmaxf(acc[r][0], 0.f); o.y = fmaxf(acc[r][1], 0.f);
            o.z = fmaxf(acc[r][2], 0.f); o.w = fmaxf(acc[r][3], 0.f);
            *(float4*)(g_rec1o + (size_t)(row0 + j0 + r) * HH + h0) = o;
        }
    }
}

// =================== kernelB: rec2 GEMM + fused ae/pred ==================
// grid (nt=2, mt=512), 256 threads, 128x128 tile, thread 8x8
__global__ void __launch_bounds__(256, 2) kernelB(const float* __restrict__ fin,
                                                  const float* __restrict__ rec2) {
    __shared__ float As[16 * 132];
    __shared__ float Bs[16 * 132];
    __shared__ float rns[128];

    int t = threadIdx.x;
    int tx = t & 15, ty = t >> 4;
    int mt = blockIdx.y, nt = blockIdx.x;
    int row0 = mt * 128;
    int n0 = nt * 128;
    int b = row0 >> 9;
    int sbase = row0 & 511;

    if (t < 128) rns[t] = g_rnorm[row0 + t];

    int rA0 = t >> 2, kkoA = t & 3;           // A-load ids (and rA0+64)
    int kkB0 = t >> 5, c4B = t & 31;          // B-load ids (and kkB0+8)

    float acc[8][8] = {};

    // prologue
    float4 a0 = *(const float4*)&g_rec1o[(size_t)(row0 + rA0) * HH + kkoA * 4];
    float4 a1 = *(const float4*)&g_rec1o[(size_t)(row0 + rA0 + 64) * HH + kkoA * 4];
    float4 b0 = *(const float4*)&rec2[(size_t)kkB0 * DD + n0 + c4B * 4];
    float4 b1 = *(const float4*)&rec2[(size_t)(kkB0 + 8) * DD + n0 + c4B * 4];
    {
        As[(kkoA * 4 + 0) * 132 + rA0] = a0.x; As[(kkoA * 4 + 1) * 132 + rA0] = a0.y;
        As[(kkoA * 4 + 2) * 132 + rA0] = a0.z; As[(kkoA * 4 + 3) * 132 + rA0] = a0.w;
        As[(kkoA * 4 + 0) * 132 + rA0 + 64] = a1.x; As[(kkoA * 4 + 1) * 132 + rA0 + 64] = a1.y;
        As[(kkoA * 4 + 2) * 132 + rA0 + 64] = a1.z; As[(kkoA * 4 + 3) * 132 + rA0 + 64] = a1.w;
        *(float4*)&Bs[kkB0 * 132 + c4B * 4] = b0;
        *(float4*)&Bs[(kkB0 + 8) * 132 + c4B * 4] = b1;
    }
    __syncthreads();

    for (int kt = 0; kt < 16; kt++) {
        if (kt < 15) {
            int k0 = (kt + 1) * 16;
            a0 = *(const float4*)&g_rec1o[(size_t)(row0 + rA0) * HH + k0 + kkoA * 4];
            a1 = *(const float4*)&g_rec1o[(size_t)(row0 + rA0 + 64) * HH + k0 + kkoA * 4];
            b0 = *(const float4*)&rec2[(size_t)(k0 + kkB0) * DD + n0 + c4B * 4];
            b1 = *(const float4*)&rec2[(size_t)(k0 + kkB0 + 8) * DD + n0 + c4B * 4];
        }
        #pragma unroll
        for (int kk = 0; kk < 16; kk++) {
            float ar[8], br[8];
            #pragma unroll
            for (int i = 0; i < 8; i++) ar[i] = As[kk * 132 + tx + 16 * i];
            float4 bv0 = *(const float4*)&Bs[kk * 132 + ty * 8];
            float4 bv1 = *(const float4*)&Bs[kk * 132 + ty * 8 + 4];
            br[0] = bv0.x; br[1] = bv0.y; br[2] = bv0.z; br[3] = bv0.w;
            br[4] = bv1.x; br[5] = bv1.y; br[6] = bv1.z; br[7] = bv1.w;
            #pragma unroll
            for (int i = 0; i < 8; i++)
                #pragma unroll
                for (int c = 0; c < 8; c++)
                    acc[i][c] += ar[i] * br[c];
        }
        __syncthreads();
        if (kt < 15) {
            As[(kkoA * 4 + 0) * 132 + rA0] = a0.x; As[(kkoA * 4 + 1) * 132 + rA0] = a0.y;
            As[(kkoA * 4 + 2) * 132 + rA0] = a0.z; As[(kkoA * 4 + 3) * 132 + rA0] = a0.w;
            As[(kkoA * 4 + 0) * 132 + rA0 + 64] = a1.x; As[(kkoA * 4 + 1) * 132 + rA0 + 64] = a1.y;
            As[(kkoA * 4 + 2) * 132 + rA0 + 64] = a1.z; As[(kkoA * 4 + 3) * 132 + rA0 + 64] = a1.w;
            *(float4*)&Bs[kkB0 * 132 + c4B * 4] = b0;
            *(float4*)&Bs[(kkB0 + 8) * 132 + c4B * 4] = b1;
            __syncthreads();
        }
    }

    // epilogue: ae partial + column sums (rec2out never stored)
    float aeacc = 0.f;
    float colsum[8] = {};
    const float* fbase = fin + (size_t)b * DD * SS;
    #pragma unroll
    for (int i = 0; i < 8; i++) {
        int r = tx + 16 * i;
        float rnv = rns[r];
        int s = sbase + r;
        #pragma unroll
        for (int c = 0; c < 8; c++) {
            int d = n0 + ty * 8 + c;
            float o = acc[i][c];
            float xn = fbase[(size_t)d * SS + s] * rnv;
            float df = xn - o;
            aeacc += df * df;
            colsum[c] += o;
        }
    }
    __syncthreads();
    // pred column-sum reduce (reuse As as [16 tx][128 d])
    #pragma unroll
    for (int c = 0; c < 8; c++) As[tx * 128 + ty * 8 + c] = colsum[c];
    Bs[t] = aeacc;
    __syncthreads();
    if (t < 128) {
        float s = 0.f;
        #pragma unroll
        for (int x = 0; x < 16; x++) s += As[x * 128 + t];
        g_predpart[mt * 256 + n0 + t] = s;
    }
    for (int off = 128; off > 0; off >>= 1) {
        if (t < off) Bs[t] += Bs[t + off];
        __syncthreads();
    }
    if (t == 0) g_aepart[mt * 2 + nt] = Bs[0];
}

// =========== top-k chain: histogram -> threshold -> collect -> select ====
// histK: per-concept 128-bin histogram of (int)(v*128), bins >= 8 only.
__global__ void __launch_bounds__(256) histK() {
    __shared__ int h[KK * 128];
    int t = threadIdx.x;
    int row0 = blockIdx.x * 256;
    for (int i = t; i < KK * 128; i += 256) h[i] = 0;
    __syncthreads();
    #pragma unroll 2
    for (int k = 0; k < KK; k++) {
        float v = g_tpnT[(size_t)k * NROW + row0 + t];
        int bin = (int)(v * 128.0f);
        if (bin >= 8) atomicAdd(&h[k * 128 + min(bin, 127)], 1);
    }
    __syncthreads();
    for (int i = t; i < KK * 128; i += 256) {
        int c = h[i];
        if (c) atomicAdd(&g_hist[i], c);
    }
}

// threshK: smallest bin b (>=8) with cumulative-from-top count >= 32; else 7.
__global__ void threshK() {
    int k = threadIdx.x;
    if (k >= KK) return;
    int cum = 0, bstar = 7;
    for (int b = 127; b >= 8; b--) {
        cum += g_hist[k * 128 + b];
        if (cum >= 32) { bstar = b; break; }
    }
    g_bstar[k] = bstar;
}

// collectK: gather all values with bin >= bstar (fallback bstar==7: all values)
__global__ void __launch_bounds__(256) collectK() {
    int t = threadIdx.x;
    int row0 = blockIdx.x * 256;
    #pragma unroll 2
    for (int k = 0; k < KK; k++) {
        float v = g_tpnT[(size_t)k * NROW + row0 + t];
        int bin = (int)(v * 128.0f);
        int bs = g_bstar[k];
        if (bin >= bs || bs == 7) {
            int idx = atomicAdd(&g_candcnt[k], 1);
            g_cand[(size_t)k * NROW + idx] = v;
        }
    }
}

// finalC: top-32 sum from the (small) candidate set via 32 block-argmax rounds
__global__ void __launch_bounds__(256) finalC() {
    int k = blockIdx.x, t = threadIdx.x;
    int C = g_candcnt[k];
    __shared__ float vals[8192];
    __shared__ float rmax[256];
    __shared__ int   rarg[256];
    float* v;
    if (C <= 8192) {
        for (int i = t; i < C; i += 256) vals[i] = g_cand[(size_t)k * NROW + i];
        v = vals;
    } else {
        v = &g_cand[(size_t)k * NROW];   // pathological fallback: operate in gmem
    }
    __syncthreads();
    float sum = 0.f;
    int rounds = C < 32 ? C : 32;
    for (int r = 0; r < rounds; r++) {
        float m = -1e30f; int mi = -1;
        for (int i = t; i < C; i += 256) {
            float x = v[i];
            if (x > m) { m = x; mi = i; }
        }
        rmax[t] = m; rarg[t] = mi;
        __syncthreads();
        for (int off = 128; off > 0; off >>= 1) {
            if (t < off && rmax[t + off] > rmax[t]) { rmax[t] = rmax[t + off]; rarg[t] = rarg[t + off]; }
            __syncthreads();
        }
        if (t == 0) { sum += rmax[0]; v[rarg[0]] = -1e30f; }
        __syncthreads();
    }
    if (t == 0) g_topsum[k] = sum;
}

// =================== final: reductions + pred head =======================
__global__ void __launch_bounds__(256) finalK(const float* __restrict__ Wc,
                                              const float* __restrict__ bc,
                                              float* __restrict__ out) {
    __shared__ float red[256];
    int t = threadIdx.x;
    float s = 0.f;
    for (int i = t; i < 1024; i += 256) s += g_aepart[i];
    red[t] = s;
    __syncthreads();
    for (int off = 128; off > 0; off >>= 1) {
        if (t < off) red[t] += red[t + off];
        __syncthreads();
    }
    if (t == 0) {
        out[OUT_AE] = red[0] / 16777216.0f;
        float cs = 0.f;
        for (int k = 0; k < KK; k++) cs += g_topsum[k];
        out[OUT_CSIM] = -cs / 1600.0f;
    }
    // pred: thread = b*2 + cls
    {
        int bi = t >> 1, c = t & 1;
        float acc = 0.f;
        for (int d = 0; d < DD; d++) {
            float rs = g_predpart[(bi * 4 + 0) * 256 + d]
                     + g_predpart[(bi * 4 + 1) * 256 + d]
                     + g_predpart[(bi * 4 + 2) * 256 + d]
                     + g_predpart[(bi * 4 + 3) * 256 + d];
            acc += rs * Wc[d * 2 + c];
        }
        out[bi * 2 + c] = acc * (1.0f / 512.0f) + bc[c];
    }
}

// ============================ launcher ===================================
extern "C" void kernel_launch(void* const* d_in, const int* in_sizes, int n_in,
                              void* d_out, int out_size) {
    const float* f_input      = (const float*)d_in[0];
    // d_in[1] targets: unused by the reference outputs
    const float* topic_vector = (const float*)d_in[2];
    const float* rec1         = (const float*)d_in[3];
    const float* rec2         = (const float*)d_in[4];
    const float* Wc           = (const float*)d_in[5];
    const float* bc           = (const float*)d_in[6];
    float* out = (float*)d_out;

    cudaFuncSetAttribute(kernelA, cudaFuncAttributeMaxDynamicSharedMemorySize, SMEM_A_BYTES);

    prep_kernel<<<1, 256>>>(topic_vector, out);
    kernelA<<<512, 512, SMEM_A_BYTES>>>(f_input, rec1, out);
    histK<<<256, 256>>>();
    threshK<<<1, 64>>>();
    collectK<<<256, 256>>>();
    finalC<<<KK, 256>>>();
    kernelB<<<dim3(2, 512), 256>>>(f_input, rec2);
    finalK<<<1, 256>>>(Wc, bc, out);
}

// round 4
// speedup vs baseline: 1.5037x; 1.2234x over previous
#include <cuda_runtime.h>
#include <cuda_bf16.h>
#include <math.h>
#include <stdint.h>

// Problem constants
#define BB   128
#define DD   256
#define SS   512
#define KK   50
#define HH   256
#define NROW 65536           // B*S
#define OUT_PRED   0         // 256 floats
#define OUT_ZERO   256
#define OUT_CSIM   257
#define OUT_CFAR   258
#define OUT_TPNN   259       // 3,276,800 floats
#define OUT_AE     3277059

// -------- scratch (static device memory; no allocations allowed) --------
__device__ float g_tvn[DD * KK];                   // normalized topic vectors [d][k]
__device__ float g_rnorm[NROW];                    // 1/max(||x_row||,1e-12)
__device__ float g_tpnT[(size_t)KK * NROW];        // topic_prob_n transposed [k][row]
__device__ __nv_bfloat16 g_rec1o_bf[(size_t)NROW * HH]; // relu(nn @ rec1) bf16 (32 MB)
__device__ __nv_bfloat16 g_rec2T_bf[DD * HH];      // rec2 transposed [d][h] bf16
__device__ float g_hpart[512 * HH];                // per-CTA fp32 colsums of rec1out
__device__ float g_rowrec[BB * DD];                // fp32 (sum_s rec1out) @ rec2
__device__ float g_aepart[1024];                   // per-CTA ae partials
__device__ float g_topsum[KK];                     // per-concept top-32 sums
// top-k selection scratch
__device__ int   g_hist[KK * 128];
__device__ int   g_bstar[KK];
__device__ int   g_candcnt[KK];
__device__ float g_cand[(size_t)KK * NROW];

// ======================= prep: tv_n + concept_far + zero scratch ========
__global__ void prep_kernel(const float* __restrict__ tv, float* __restrict__ out) {
    __shared__ float cinv[64];
    __shared__ float sd[DD];
    int t = threadIdx.x;                 // 256 threads
    for (int i = t; i < KK * 128; i += 256) g_hist[i] = 0;
    if (t < KK) g_candcnt[t] = 0;
    if (t < KK) {
        float s = 0.f;
        for (int d = 0; d < DD; d++) { float v = tv[d * KK + t]; s += v * v; }
        cinv[t] = 1.0f / fmaxf(sqrtf(s), 1e-12f);
    }
    __syncthreads();
    {   // thread t == d
        float sum = 0.f;
        for (int k = 0; k < KK; k++) {
            float v = tv[t * KK + k] * cinv[k];
            g_tvn[t * KK + k] = v;
            sum += v;
        }
        sd[t] = sum;
    }
    __syncthreads();
    if (t == 0) {
        float g = 0.f;
        for (int d = 0; d < DD; d++) g += sd[d] * sd[d];
        out[OUT_CFAR] = (g - (float)KK) / (float)(KK * KK);
        out[OUT_ZERO] = 0.0f;
    }
}

// ================ convT: rec2 [H][D] fp32 -> [D][H] bf16 ================
__global__ void convT(const float* __restrict__ rec2) {
    int d = blockIdx.x, h = threadIdx.x;   // 256 blocks x 256 threads
    g_rec2T_bf[d * HH + h] = __float2bfloat16(rec2[h * DD + d]);
}

// =================== kernelA: topic path + rec1 =========================
#define XS_F  (256 * 128)
#define TVS_F (256 * 52)
#define TPS_F (128 * 52)
#define SMEM_A_BYTES ((XS_F + TVS_F + TPS_F + 128 + 512) * 4)

__global__ void __launch_bounds__(512) kernelA(const float* __restrict__ fin,
                                               const float* __restrict__ rec1,
                                               float* __restrict__ out) {
    extern __shared__ float sm[];
    float* xs  = sm;                   // [256 d][128 j]
    float* tvs = xs + XS_F;            // [256 d][52 k] (later rec1 [50][256])
    float* tps = tvs + TVS_F;          // [128 j][52 k] (later colsum scratch)
    float* rn  = tps + TPS_F;          // [128]
    float* ps  = rn + 128;             // [128][4]

    int t = threadIdx.x;
    int cid = blockIdx.x;
    int b = cid >> 2, st = cid & 3;
    int s0 = st * 128;
    int row0 = b * SS + s0;
    const float* fb = fin + (size_t)b * DD * SS + s0;

    #pragma unroll 4
    for (int it = 0; it < 64; it++) {
        int idx = t + 512 * it;
        int d = idx >> 7, j = idx & 127;
        xs[d * 128 + j] = fb[(size_t)d * SS + j];
    }
    for (int idx = t; idx < TVS_F; idx += 512) {
        int d = idx / 52, k = idx - d * 52;
        tvs[idx] = (k < KK) ? g_tvn[d * KK + k] : 0.0f;
    }
    __syncthreads();

    {
        int j = t >> 2, q = t & 3;
        const float* xp = xs + (q * 64) * 128 + j;
        float s = 0.f;
        #pragma unroll 8
        for (int d = 0; d < 64; d++) { float v = xp[d * 128]; s += v * v; }
        ps[j * 4 + q] = s;
    }
    __syncthreads();
    if (t < 128) {
        float s = ps[t * 4] + ps[t * 4 + 1] + ps[t * 4 + 2] + ps[t * 4 + 3];
        float r = 1.0f / fmaxf(sqrtf(s), 1e-12f);
        rn[t] = r;
        g_rnorm[row0 + t] = r;
    }
    __syncthreads();

    if (t < 416) {
        int jt = t / 13, kt = t - jt * 13;
        const float* xb = xs + jt * 4;
        const float* tb = tvs + kt * 4;
        float acc[4][4] = {};
        #pragma unroll 4
        for (int d = 0; d < DD; d++) {
            float4 xv = *(const float4*)(xb + d * 128);
            float4 tw = *(const float4*)(tb + d * 52);
            float xr[4] = {xv.x, xv.y, xv.z, xv.w};
            float tr[4] = {tw.x, tw.y, tw.z, tw.w};
            #pragma unroll
            for (int r = 0; r < 4; r++)
                #pragma unroll
                for (int c = 0; c < 4; c++)
                    acc[r][c] += xr[r] * tr[c];
        }
        #pragma unroll
        for (int r = 0; r < 4; r++)
            #pragma unroll
            for (int c = 0; c < 4; c++)
                tps[(jt * 4 + r) * 52 + kt * 4 + c] = acc[r][c];
    }
    __syncthreads();

    int j = t >> 2, q = t & 3;
    int gRow = row0 + j;
    {
        float partial = 0.f;
        float rj = rn[j];
        #pragma unroll
        for (int i = 0; i < 13; i++) {
            int k = q + 4 * i;
            if (k < KK) {
                float tp = tps[j * 52 + k];
                float tpn = tp * rj;
                g_tpnT[(size_t)k * NROW + gRow] = tpn;
                float m = (tpn > 0.3f) ? tp : 0.0f;
                tps[j * 52 + k] = m;
                partial += m;
            }
        }
        ps[j * 4 + q] = partial;
    }
    __syncthreads();
    if (t < 128) {
        float s = ps[t * 4] + ps[t * 4 + 1] + ps[t * 4 + 2] + ps[t * 4 + 3];
        rn[t] = 1.0f / (s + 0.001f + 1e-8f);
    }
    __syncthreads();
    {
        float inv = rn[j];
        float* tpnn = out + OUT_TPNN;
        #pragma unroll
        for (int i = 0; i < 13; i++) {
            int k = q + 4 * i;
            if (k < KK) {
                float nv = tps[j * 52 + k] * inv;
                tps[j * 52 + k] = nv;
                tpnn[(size_t)gRow * KK + k] = nv;
            }
        }
    }
    __syncthreads();

    for (int idx = t; idx < KK * HH; idx += 512) tvs[idx] = rec1[idx];
    __syncthreads();

    // rec1out = relu(nn @ rec1): bf16 store + fp32 column-sum partials.
    // idx = t + 512*it  ->  jt = (t>>6) + 8*it, ht = t&63  (ht fixed per thread)
    float colp[4] = {};
    #pragma unroll
    for (int it = 0; it < 4; it++) {
        int idx = t + 512 * it;
        int jt = idx >> 6, ht = idx & 63;
        int j0 = jt * 4, h0 = ht * 4;
        float acc[4][4] = {};
        #pragma unroll 2
        for (int k = 0; k < KK; k++) {
            float nv[4];
            #pragma unroll
            for (int r = 0; r < 4; r++) nv[r] = tps[(j0 + r) * 52 + k];
            float4 rv = *(const float4*)(tvs + k * HH + h0);
            float rr[4] = {rv.x, rv.y, rv.z, rv.w};
            #pragma unroll
            for (int r = 0; r < 4; r++)
                #pragma unroll
                for (int c = 0; c < 4; c++)
                    acc[r][c] += nv[r] * rr[c];
        }
        #pragma unroll
        for (int r = 0; r < 4; r++) {
            float v0 = fmaxf(acc[r][0], 0.f), v1 = fmaxf(acc[r][1], 0.f);
            float v2 = fmaxf(acc[r][2], 0.f), v3 = fmaxf(acc[r][3], 0.f);
            colp[0] += v0; colp[1] += v1; colp[2] += v2; colp[3] += v3;
            __nv_bfloat162 p0 = __floats2bfloat162_rn(v0, v1);
            __nv_bfloat162 p1 = __floats2bfloat162_rn(v2, v3);
            uint2 pk;
            pk.x = *(uint32_t*)&p0;
            pk.y = *(uint32_t*)&p1;
            *(uint2*)(g_rec1o_bf + (size_t)(row0 + j0 + r) * HH + h0) = pk;
        }
    }
    __syncthreads();          // all reads of tps done; reuse as colsum scratch
    // ps2[h][q], h = (t&63)*4+c, q = t>>6  (8 partials per h)
    {
        float* ps2 = tps;     // needs 256*8 = 2048 floats <= TPS_F
        int ht = t & 63, qq = t >> 6;
        #pragma unroll
        for (int c = 0; c < 4; c++) ps2[(ht * 4 + c) * 8 + qq] = colp[c];
        __syncthreads();
        if (t < 256) {
            float s = 0.f;
            #pragma unroll
            for (int q2 = 0; q2 < 8; q2++) s += ps2[t * 8 + q2];
            g_hpart[cid * HH + t] = s;
        }
    }
}

// ============ predK: rowrec[b][d] = (sum_s rec1out) @ rec2 (fp32 exact) ==
__global__ void __launch_bounds__(256) predK(const float* __restrict__ rec2) {
    __shared__ float hs[HH];
    int b = blockIdx.x, d = threadIdx.x;
    hs[d] = g_hpart[(b * 4 + 0) * HH + d] + g_hpart[(b * 4 + 1) * HH + d]
          + g_hpart[(b * 4 + 2) * HH + d] + g_hpart[(b * 4 + 3) * HH + d];
    __syncthreads();
    float acc = 0.f;
    #pragma unroll 8
    for (int h = 0; h < HH; h++) acc += hs[h] * rec2[h * DD + d];
    g_rowrec[b * DD + d] = acc;
}

// =================== kernelB: bf16 tensor-core GEMM + fused ae ==========
__device__ __forceinline__ void mma_bf16(float* c, uint32_t a0, uint32_t a1,
                                         uint32_t a2, uint32_t a3,
                                         uint32_t b0, uint32_t b1) {
    asm volatile(
        "mma.sync.aligned.m16n8k16.row.col.f32.bf16.bf16.f32 "
        "{%0,%1,%2,%3},{%4,%5,%6,%7},{%8,%9},{%0,%1,%2,%3};"
        : "+f"(c[0]), "+f"(c[1]), "+f"(c[2]), "+f"(c[3])
        : "r"(a0), "r"(a1), "r"(a2), "r"(a3), "r"(b0), "r"(b1));
}

__global__ void __launch_bounds__(256) kernelB(const float* __restrict__ fin) {
    __shared__ float rns[128];
    __shared__ float aew[8];

    int t = threadIdx.x;
    int warp = t >> 5, lane = t & 31;
    int g = lane >> 2, tid = lane & 3;
    int wm = warp >> 2, wn = warp & 3;
    int mt = blockIdx.y, nt_blk = blockIdx.x;
    int row0 = mt * 128;
    int n0 = nt_blk * 128;
    int b = row0 >> 9;
    int sbase = row0 & 511;

    if (t < 128) rns[t] = g_rnorm[row0 + t];

    float acc[4][4][4] = {};

    const __nv_bfloat16* Abase = g_rec1o_bf + (size_t)(row0 + wm * 64) * HH;
    const __nv_bfloat16* Bbase = g_rec2T_bf + (size_t)(n0 + wn * 32) * HH;

    #pragma unroll 1
    for (int k0 = 0; k0 < HH; k0 += 16) {
        uint32_t bf[4][2];
        #pragma unroll
        for (int nt = 0; nt < 4; nt++) {
            const __nv_bfloat16* bp = Bbase + (nt * 8 + g) * HH + k0 + tid * 2;
            bf[nt][0] = *(const uint32_t*)bp;
            bf[nt][1] = *(const uint32_t*)(bp + 8);
        }
        #pragma unroll
        for (int mtile = 0; mtile < 4; mtile++) {
            const __nv_bfloat16* ap = Abase + (mtile * 16 + g) * HH + k0 + tid * 2;
            uint32_t a0 = *(const uint32_t*)ap;
            uint32_t a1 = *(const uint32_t*)(ap + 8 * HH);
            uint32_t a2 = *(const uint32_t*)(ap + 8);
            uint32_t a3 = *(const uint32_t*)(ap + 8 * HH + 8);
            #pragma unroll
            for (int nt = 0; nt < 4; nt++)
                mma_bf16(acc[mtile][nt], a0, a1, a2, a3, bf[nt][0], bf[nt][1]);
        }
    }

    // ---- epilogue: ae partials only ----
    float aeacc = 0.f;
    const float* fbase = fin + (size_t)b * DD * SS;
    #pragma unroll
    for (int mtile = 0; mtile < 4; mtile++) {
        #pragma unroll
        for (int half = 0; half < 2; half++) {
            int r = wm * 64 + mtile * 16 + g + half * 8;
            float rnv = rns[r];
            int s = sbase + r;
            #pragma unroll
            for (int nt = 0; nt < 4; nt++) {
                #pragma unroll
                for (int c = 0; c < 2; c++) {
                    int d = n0 + wn * 32 + nt * 8 + tid * 2 + c;
                    float o = acc[mtile][nt][half * 2 + c];
                    float xn = fbase[(size_t)d * SS + s] * rnv;
                    float df = xn - o;
                    aeacc += df * df;
                }
            }
        }
    }
    #pragma unroll
    for (int off = 16; off >= 1; off >>= 1)
        aeacc += __shfl_xor_sync(0xffffffffu, aeacc, off);
    if (lane == 0) aew[warp] = aeacc;
    __syncthreads();
    if (t == 0) {
        float s = 0.f;
        #pragma unroll
        for (int w = 0; w < 8; w++) s += aew[w];
        g_aepart[mt * 2 + nt_blk] = s;
    }
}

// =========== top-k chain: histogram -> threshold -> collect -> select ====
__global__ void __launch_bounds__(256) histK() {
    __shared__ int h[KK * 128];
    int t = threadIdx.x;
    int row0 = blockIdx.x * 256;
    for (int i = t; i < KK * 128; i += 256) h[i] = 0;
    __syncthreads();
    #pragma unroll 2
    for (int k = 0; k < KK; k++) {
        float v = g_tpnT[(size_t)k * NROW + row0 + t];
        int bin = (int)(v * 128.0f);
        if (bin >= 8) atomicAdd(&h[k * 128 + min(bin, 127)], 1);
    }
    __syncthreads();
    for (int i = t; i < KK * 128; i += 256) {
        int c = h[i];
        if (c) atomicAdd(&g_hist[i], c);
    }
}

__global__ void threshK() {
    int k = blockIdx.x;
    int lane = threadIdx.x;
    int cum = 0, bstar = 7;
    for (int base = 127; base >= 8 && bstar == 7; base -= 32) {
        int bb = base - lane;
        int cnt = (bb >= 8) ? g_hist[k * 128 + bb] : 0;
        int incl = cnt;
        #pragma unroll
        for (int off = 1; off < 32; off <<= 1) {
            int v = __shfl_up_sync(0xffffffffu, incl, off);
            if (lane >= off) incl += v;
        }
        int total = __shfl_sync(0xffffffffu, incl, 31);
        unsigned mask = __ballot_sync(0xffffffffu, (cum + incl >= 32) && bb >= 8);
        if (mask) bstar = base - (__ffs(mask) - 1);
        cum += total;
    }
    if (lane == 0) g_bstar[k] = bstar;
}

__global__ void __launch_bounds__(256) collectK() {
    int t = threadIdx.x;
    int row0 = blockIdx.x * 256;
    #pragma unroll 2
    for (int k = 0; k < KK; k++) {
        float v = g_tpnT[(size_t)k * NROW + row0 + t];
        int bin = (int)(v * 128.0f);
        int bs = g_bstar[k];
        if (bin >= bs || bs == 7) {
            int idx = atomicAdd(&g_candcnt[k], 1);
            g_cand[(size_t)k * NROW + idx] = v;
        }
    }
}

__global__ void __launch_bounds__(256) finalC() {
    int k = blockIdx.x, t = threadIdx.x;
    int C = g_candcnt[k];
    __shared__ float vals[8192];
    __shared__ float rmax[256];
    __shared__ int   rarg[256];
    float* v;
    if (C <= 8192) {
        for (int i = t; i < C; i += 256) vals[i] = g_cand[(size_t)k * NROW + i];
        v = vals;
    } else {
        v = &g_cand[(size_t)k * NROW];
    }
    __syncthreads();
    float sum = 0.f;
    int rounds = C < 32 ? C : 32;
    for (int r = 0; r < rounds; r++) {
        float m = -1e30f; int mi = -1;
        for (int i = t; i < C; i += 256) {
            float x = v[i];
            if (x > m) { m = x; mi = i; }
        }
        rmax[t] = m; rarg[t] = mi;
        __syncthreads();
        for (int off = 128; off > 0; off >>= 1) {
            if (t < off && rmax[t + off] > rmax[t]) { rmax[t] = rmax[t + off]; rarg[t] = rarg[t + off]; }
            __syncthreads();
        }
        if (t == 0) { sum += rmax[0]; v[rarg[0]] = -1e30f; }
        __syncthreads();
    }
    if (t == 0) g_topsum[k] = sum;
}

// =================== final: reductions + pred head =======================
__global__ void __launch_bounds__(256) finalK(const float* __restrict__ Wc,
                                              const float* __restrict__ bc,
                                              float* __restrict__ out) {
    __shared__ float red[256];
    int t = threadIdx.x;
    float s = 0.f;
    for (int i = t; i < 1024; i += 256) s += g_aepart[i];
    red[t] = s;
    __syncthreads();
    for (int off = 128; off > 0; off >>= 1) {
        if (t < off) red[t] += red[t + off];
        __syncthreads();
    }
    if (t == 0) {
        out[OUT_AE] = red[0] / 16777216.0f;
        float cs = 0.f;
        for (int k = 0; k < KK; k++) cs += g_topsum[k];
        out[OUT_CSIM] = -cs / 1600.0f;
    }
    {
        int bi = t >> 1, c = t & 1;
        float acc = 0.f;
        for (int d = 0; d < DD; d++)
            acc += g_rowrec[bi * DD + d] * Wc[d * 2 + c];
        out[bi * 2 + c] = acc * (1.0f / 512.0f) + bc[c];
    }
}

// ============================ launcher ===================================
extern "C" void kernel_launch(void* const* d_in, const int* in_sizes, int n_in,
                              void* d_out, int out_size) {
    const float* f_input      = (const float*)d_in[0];
    const float* topic_vector = (const float*)d_in[2];
    const float* rec1         = (const float*)d_in[3];
    const float* rec2         = (const float*)d_in[4];
    const float* Wc           = (const float*)d_in[5];
    const float* bc           = (const float*)d_in[6];
    float* out = (float*)d_out;

    cudaFuncSetAttribute(kernelA, cudaFuncAttributeMaxDynamicSharedMemorySize, SMEM_A_BYTES);

    prep_kernel<<<1, 256>>>(topic_vector, out);
    convT<<<256, 256>>>(rec2);
    kernelA<<<512, 512, SMEM_A_BYTES>>>(f_input, rec1, out);
    histK<<<256, 256>>>();
    threshK<<<KK, 32>>>();
    collectK<<<256, 256>>>();
    finalC<<<KK, 256>>>();
    kernelB<<<dim3(2, 512), 256>>>(f_input);
    predK<<<BB, 256>>>(rec2);
    finalK<<<1, 256>>>(Wc, bc, out);
}